// round 4
// baseline (speedup 1.0000x reference)
#include <cuda_runtime.h>
#include <cstdint>

#define NN 50000
#define EE 800000
#define DIM 128

// Scratch (static device globals — no allocation at launch time).
__device__ float g_buf[3u * NN * DIM];        // per-type scatter accumulators, 76.8 MB
__device__ float cnt_buf[3u * NN];            // per-type in-degree counts (float, exact)
__device__ float wcat_buf[4 * DIM * DIM];     // concatenated weights, [k][o] layout, k=0..511

// ---------------------------------------------------------------------------
// Phase 0: zero accumulators
// ---------------------------------------------------------------------------
__global__ void zero_kernel() {
    const float4 z = make_float4(0.f, 0.f, 0.f, 0.f);
    size_t i = (size_t)blockIdx.x * blockDim.x + threadIdx.x;
    const size_t ng = (size_t)3 * NN * DIM / 4;   // 4.8M float4
    if (i < ng) reinterpret_cast<float4*>(g_buf)[i] = z;
    if (i < (size_t)(3 * NN) / 4) reinterpret_cast<float4*>(cnt_buf)[i] = z;
}

// ---------------------------------------------------------------------------
// Phase 0b: build Wcat[k][o] = W_{k/128}[o][k%128]  (k-major, o contiguous)
// ---------------------------------------------------------------------------
__global__ void wprep_kernel(const float* __restrict__ W0, const float* __restrict__ W1,
                             const float* __restrict__ W2, const float* __restrict__ Wh) {
    int idx = blockIdx.x * blockDim.x + threadIdx.x;   // < 512*128
    int k = idx >> 7;          // 0..511
    int o = idx & 127;
    int t = k >> 7;            // segment 0..3
    int kk = k & 127;
    const float* W = (t == 0) ? W0 : (t == 1) ? W1 : (t == 2) ? W2 : Wh;
    wcat_buf[idx] = W[o * DIM + kk];
}

// ---------------------------------------------------------------------------
// Phase 1: edge scatter. One warp per edge.
//   G_t[dst] += x[src] - x[dst];  cnt_t[dst] += 1
// ---------------------------------------------------------------------------
__global__ __launch_bounds__(256) void scatter_kernel(
    const float4* __restrict__ x4,
    const int* __restrict__ src, const int* __restrict__ dst,
    const int* __restrict__ et) {
    int warp = (int)(((size_t)blockIdx.x * blockDim.x + threadIdx.x) >> 5);
    int lane = threadIdx.x & 31;
    if (warp >= EE) return;
    int s = __ldg(src + warp);
    int d = __ldg(dst + warp);
    int t = __ldg(et + warp);

    float4 a = x4[(size_t)s * 32 + lane];
    float4 b = x4[(size_t)d * 32 + lane];
    float4 v;
    v.x = a.x - b.x; v.y = a.y - b.y; v.z = a.z - b.z; v.w = a.w - b.w;

    float* p = g_buf + ((size_t)t * NN + d) * DIM + lane * 4;
    asm volatile("red.global.add.v4.f32 [%0], {%1, %2, %3, %4};"
                 :: "l"(p), "f"(v.x), "f"(v.y), "f"(v.z), "f"(v.w) : "memory");

    if (lane == 0) atomicAdd(cnt_buf + (size_t)t * NN + d, 1.0f);
}

// ---------------------------------------------------------------------------
// Phase 2: out[N,128] = A[N,512] @ Wcat[512,128] + bias(counts)
//   A[v, k] = G_{k/128}[v][k%128]  for k<384,  x[v][k-384] for k>=384
// Tiling: BM=64 nodes x BN=128 outs per CTA, BK=16, 256 threads, 4x8 microtile.
// ---------------------------------------------------------------------------
__global__ __launch_bounds__(256) void gemm_kernel(
    const float* __restrict__ x,
    const float* __restrict__ b0, const float* __restrict__ b1,
    const float* __restrict__ b2, const float* __restrict__ bh,
    float* __restrict__ out) {
    __shared__ float As[2][16][68];    // padded 64+4 to avoid write conflicts
    __shared__ float Bs[2][16][128];
    __shared__ float bias_s[4][128];

    const int tid = threadIdx.x;
    if (tid < 128) {
        bias_s[0][tid] = b0[tid];
        bias_s[1][tid] = b1[tid];
        bias_s[2][tid] = b2[tid];
        bias_s[3][tid] = bh[tid];
    }

    const int node0 = blockIdx.x * 64;
    const int m0 = (tid >> 4) * 4;       // 0..60
    const int n0 = (tid & 15) * 8;       // 0..120

    // A-load mapping: each thread loads one float4 of a 64x16 tile
    const int a_m = tid >> 2;            // 0..63 (node row within tile)
    const int a_q = tid & 3;             // float4 index along k
    // B-load mapping: each thread loads two float4 of a 16x128 tile
    const int b_k = tid >> 5;            // 0..7
    const int b_o = (tid & 31) * 4;      // 0..124

    float acc[4][8];
#pragma unroll
    for (int i = 0; i < 4; i++)
#pragma unroll
        for (int j = 0; j < 8; j++) acc[i][j] = 0.f;

    const int av = node0 + a_m;
    const bool a_ok = (av < NN);

    // ---- tile loaders ----
    auto loadA = [&](int kt, int buf) {
        int kg = kt * 16 + a_q * 4;
        int seg = kg >> 7;
        int kk = kg & 127;
        float4 val = make_float4(0.f, 0.f, 0.f, 0.f);
        if (a_ok) {
            const float* ap = (seg < 3)
                ? (g_buf + ((size_t)seg * NN + av) * DIM + kk)
                : (x + (size_t)av * DIM + kk);
            val = *reinterpret_cast<const float4*>(ap);
        }
        As[buf][a_q * 4 + 0][a_m] = val.x;
        As[buf][a_q * 4 + 1][a_m] = val.y;
        As[buf][a_q * 4 + 2][a_m] = val.z;
        As[buf][a_q * 4 + 3][a_m] = val.w;
    };
    auto loadB = [&](int kt, int buf) {
#pragma unroll
        for (int r = 0; r < 2; r++) {
            int k = b_k + r * 8;
            float4 w = *reinterpret_cast<const float4*>(
                wcat_buf + (size_t)(kt * 16 + k) * DIM + b_o);
            *reinterpret_cast<float4*>(&Bs[buf][k][b_o]) = w;
        }
    };

    loadA(0, 0);
    loadB(0, 0);
    __syncthreads();

#pragma unroll 4
    for (int kt = 0; kt < 32; kt++) {
        int cur = kt & 1;
        int nxt = cur ^ 1;
        if (kt + 1 < 32) {
            loadA(kt + 1, nxt);
            loadB(kt + 1, nxt);
        }
#pragma unroll
        for (int k = 0; k < 16; k++) {
            float4 ra = *reinterpret_cast<const float4*>(&As[cur][k][m0]);
            float4 rb0 = *reinterpret_cast<const float4*>(&Bs[cur][k][n0]);
            float4 rb1 = *reinterpret_cast<const float4*>(&Bs[cur][k][n0 + 4]);
            float ar[4] = {ra.x, ra.y, ra.z, ra.w};
            float br[8] = {rb0.x, rb0.y, rb0.z, rb0.w, rb1.x, rb1.y, rb1.z, rb1.w};
#pragma unroll
            for (int i = 0; i < 4; i++)
#pragma unroll
                for (int j = 0; j < 8; j++)
                    acc[i][j] = fmaf(ar[i], br[j], acc[i][j]);
        }
        __syncthreads();
    }

    // ---- epilogue: add count-weighted biases, store ----
#pragma unroll
    for (int i = 0; i < 4; i++) {
        int v = node0 + m0 + i;
        if (v < NN) {
            float c0 = cnt_buf[0 * NN + v];
            float c1 = cnt_buf[1 * NN + v];
            float c2 = cnt_buf[2 * NN + v];
            float res[8];
#pragma unroll
            for (int j = 0; j < 8; j++) {
                int o = n0 + j;
                res[j] = acc[i][j]
                       + c0 * bias_s[0][o]
                       + c1 * bias_s[1][o]
                       + c2 * bias_s[2][o]
                       + bias_s[3][o];
            }
            float* op = out + (size_t)v * DIM + n0;
            *reinterpret_cast<float4*>(op)     = make_float4(res[0], res[1], res[2], res[3]);
            *reinterpret_cast<float4*>(op + 4) = make_float4(res[4], res[5], res[6], res[7]);
        }
    }
}

// ---------------------------------------------------------------------------
// Launch
// ---------------------------------------------------------------------------
extern "C" void kernel_launch(void* const* d_in, const int* in_sizes, int n_in,
                              void* d_out, int out_size) {
    const float* n_feats = (const float*)d_in[0];
    const int*   src     = (const int*)d_in[1];
    const int*   dst     = (const int*)d_in[2];
    const int*   e_feats = (const int*)d_in[3];
    const float* W0 = (const float*)d_in[4];
    const float* b0 = (const float*)d_in[5];
    const float* W1 = (const float*)d_in[6];
    const float* b1 = (const float*)d_in[7];
    const float* W2 = (const float*)d_in[8];
    const float* b2 = (const float*)d_in[9];
    const float* Wh = (const float*)d_in[10];
    const float* bh = (const float*)d_in[11];
    float* out = (float*)d_out;

    // Phase 0: zero scratch (4.8M float4 for g_buf; cnt folded in)
    {
        int total = 3 * NN * DIM / 4;
        int grid = (total + 255) / 256;
        zero_kernel<<<grid, 256>>>();
    }
    // Phase 0b: weight concat
    wprep_kernel<<<(4 * DIM * DIM) / 256, 256>>>(W0, W1, W2, Wh);

    // Phase 1: edge scatter — one warp per edge
    {
        int grid = EE / 8;   // 8 warps (edges) per 256-thread block
        scatter_kernel<<<grid, 256>>>((const float4*)n_feats, src, dst, e_feats);
    }

    // Phase 2: fused GEMM + bias epilogue
    {
        int grid = (NN + 63) / 64;   // 782
        gemm_kernel<<<grid, 256>>>(n_feats, b0, b1, b2, bh, out);
    }
}

// round 5
// speedup vs baseline: 1.0052x; 1.0052x over previous
#include <cuda_runtime.h>
#include <cstdint>

#define NN 50000
#define EE 800000
#define DIM 128

// Scratch (static device globals — no allocation at launch time).
__device__ float g_buf[3u * NN * DIM];        // per-type scatter accumulators, 76.8 MB
__device__ float cnt_buf[3u * NN];            // per-type in-degree counts (float, exact)
__device__ float wcat_buf[4 * DIM * DIM];     // concatenated weights, [k][o] layout, k=0..511

// ---------------------------------------------------------------------------
// Phase 0: zero accumulators
// ---------------------------------------------------------------------------
__global__ void zero_kernel() {
    const float4 z = make_float4(0.f, 0.f, 0.f, 0.f);
    size_t i = (size_t)blockIdx.x * blockDim.x + threadIdx.x;
    const size_t ng = (size_t)3 * NN * DIM / 4;   // 4.8M float4
    if (i < ng) reinterpret_cast<float4*>(g_buf)[i] = z;
    if (i < (size_t)(3 * NN) / 4) reinterpret_cast<float4*>(cnt_buf)[i] = z;
}

// ---------------------------------------------------------------------------
// Phase 0b: build Wcat[k][o] = W_{k/128}[o][k%128]  (k-major, o contiguous)
// ---------------------------------------------------------------------------
__global__ void wprep_kernel(const float* __restrict__ W0, const float* __restrict__ W1,
                             const float* __restrict__ W2, const float* __restrict__ Wh) {
    int idx = blockIdx.x * blockDim.x + threadIdx.x;   // < 512*128
    int k = idx >> 7;          // 0..511
    int o = idx & 127;
    int t = k >> 7;            // segment 0..3
    int kk = k & 127;
    const float* W = (t == 0) ? W0 : (t == 1) ? W1 : (t == 2) ? W2 : Wh;
    wcat_buf[idx] = W[o * DIM + kk];
}

// ---------------------------------------------------------------------------
// Phase 1: edge scatter. One warp per edge.
//   G_t[dst] += x[src] - x[dst];  cnt_t[dst] += 1
// ---------------------------------------------------------------------------
__global__ __launch_bounds__(256) void scatter_kernel(
    const float4* __restrict__ x4,
    const int* __restrict__ src, const int* __restrict__ dst,
    const int* __restrict__ et) {
    int warp = (int)(((size_t)blockIdx.x * blockDim.x + threadIdx.x) >> 5);
    int lane = threadIdx.x & 31;
    if (warp >= EE) return;
    int s = __ldg(src + warp);
    int d = __ldg(dst + warp);
    int t = __ldg(et + warp);

    float4 a = x4[(size_t)s * 32 + lane];
    float4 b = x4[(size_t)d * 32 + lane];
    float4 v;
    v.x = a.x - b.x; v.y = a.y - b.y; v.z = a.z - b.z; v.w = a.w - b.w;

    float* p = g_buf + ((size_t)t * NN + d) * DIM + lane * 4;
    asm volatile("red.global.add.v4.f32 [%0], {%1, %2, %3, %4};"
                 :: "l"(p), "f"(v.x), "f"(v.y), "f"(v.z), "f"(v.w) : "memory");

    if (lane == 0) atomicAdd(cnt_buf + (size_t)t * NN + d, 1.0f);
}

// ---------------------------------------------------------------------------
// Phase 2: out[N,128] = A[N,512] @ Wcat[512,128] + bias(counts)
//   A[v, k] = G_{k/128}[v][k%128]  for k<384,  x[v][k-384] for k>=384
// Tiling: BM=64 nodes x BN=128 outs per CTA, BK=16, 256 threads, 4x8 microtile.
// ---------------------------------------------------------------------------
__global__ __launch_bounds__(256) void gemm_kernel(
    const float* __restrict__ x,
    const float* __restrict__ b0, const float* __restrict__ b1,
    const float* __restrict__ b2, const float* __restrict__ bh,
    float* __restrict__ out) {
    __shared__ float As[2][16][68];    // padded 64+4 to avoid write conflicts
    __shared__ float Bs[2][16][128];
    __shared__ float bias_s[4][128];

    const int tid = threadIdx.x;
    if (tid < 128) {
        bias_s[0][tid] = b0[tid];
        bias_s[1][tid] = b1[tid];
        bias_s[2][tid] = b2[tid];
        bias_s[3][tid] = bh[tid];
    }

    const int node0 = blockIdx.x * 64;
    const int m0 = (tid >> 4) * 4;       // 0..60
    const int n0 = (tid & 15) * 8;       // 0..120

    // A-load mapping: each thread loads one float4 of a 64x16 tile
    const int a_m = tid >> 2;            // 0..63 (node row within tile)
    const int a_q = tid & 3;             // float4 index along k
    // B-load mapping: each thread loads two float4 of a 16x128 tile
    const int b_k = tid >> 5;            // 0..7
    const int b_o = (tid & 31) * 4;      // 0..124

    float acc[4][8];
#pragma unroll
    for (int i = 0; i < 4; i++)
#pragma unroll
        for (int j = 0; j < 8; j++) acc[i][j] = 0.f;

    const int av = node0 + a_m;
    const bool a_ok = (av < NN);

    // ---- tile loaders ----
    auto loadA = [&](int kt, int buf) {
        int kg = kt * 16 + a_q * 4;
        int seg = kg >> 7;
        int kk = kg & 127;
        float4 val = make_float4(0.f, 0.f, 0.f, 0.f);
        if (a_ok) {
            const float* ap = (seg < 3)
                ? (g_buf + ((size_t)seg * NN + av) * DIM + kk)
                : (x + (size_t)av * DIM + kk);
            val = *reinterpret_cast<const float4*>(ap);
        }
        As[buf][a_q * 4 + 0][a_m] = val.x;
        As[buf][a_q * 4 + 1][a_m] = val.y;
        As[buf][a_q * 4 + 2][a_m] = val.z;
        As[buf][a_q * 4 + 3][a_m] = val.w;
    };
    auto loadB = [&](int kt, int buf) {
#pragma unroll
        for (int r = 0; r < 2; r++) {
            int k = b_k + r * 8;
            float4 w = *reinterpret_cast<const float4*>(
                wcat_buf + (size_t)(kt * 16 + k) * DIM + b_o);
            *reinterpret_cast<float4*>(&Bs[buf][k][b_o]) = w;
        }
    };

    loadA(0, 0);
    loadB(0, 0);
    __syncthreads();

#pragma unroll 4
    for (int kt = 0; kt < 32; kt++) {
        int cur = kt & 1;
        int nxt = cur ^ 1;
        if (kt + 1 < 32) {
            loadA(kt + 1, nxt);
            loadB(kt + 1, nxt);
        }
#pragma unroll
        for (int k = 0; k < 16; k++) {
            float4 ra = *reinterpret_cast<const float4*>(&As[cur][k][m0]);
            float4 rb0 = *reinterpret_cast<const float4*>(&Bs[cur][k][n0]);
            float4 rb1 = *reinterpret_cast<const float4*>(&Bs[cur][k][n0 + 4]);
            float ar[4] = {ra.x, ra.y, ra.z, ra.w};
            float br[8] = {rb0.x, rb0.y, rb0.z, rb0.w, rb1.x, rb1.y, rb1.z, rb1.w};
#pragma unroll
            for (int i = 0; i < 4; i++)
#pragma unroll
                for (int j = 0; j < 8; j++)
                    acc[i][j] = fmaf(ar[i], br[j], acc[i][j]);
        }
        __syncthreads();
    }

    // ---- epilogue: add count-weighted biases, store ----
#pragma unroll
    for (int i = 0; i < 4; i++) {
        int v = node0 + m0 + i;
        if (v < NN) {
            float c0 = cnt_buf[0 * NN + v];
            float c1 = cnt_buf[1 * NN + v];
            float c2 = cnt_buf[2 * NN + v];
            float res[8];
#pragma unroll
            for (int j = 0; j < 8; j++) {
                int o = n0 + j;
                res[j] = acc[i][j]
                       + c0 * bias_s[0][o]
                       + c1 * bias_s[1][o]
                       + c2 * bias_s[2][o]
                       + bias_s[3][o];
            }
            float* op = out + (size_t)v * DIM + n0;
            *reinterpret_cast<float4*>(op)     = make_float4(res[0], res[1], res[2], res[3]);
            *reinterpret_cast<float4*>(op + 4) = make_float4(res[4], res[5], res[6], res[7]);
        }
    }
}

// ---------------------------------------------------------------------------
// Launch
// ---------------------------------------------------------------------------
extern "C" void kernel_launch(void* const* d_in, const int* in_sizes, int n_in,
                              void* d_out, int out_size) {
    const float* n_feats = (const float*)d_in[0];
    const int*   src     = (const int*)d_in[1];
    const int*   dst     = (const int*)d_in[2];
    const int*   e_feats = (const int*)d_in[3];
    const float* W0 = (const float*)d_in[4];
    const float* b0 = (const float*)d_in[5];
    const float* W1 = (const float*)d_in[6];
    const float* b1 = (const float*)d_in[7];
    const float* W2 = (const float*)d_in[8];
    const float* b2 = (const float*)d_in[9];
    const float* Wh = (const float*)d_in[10];
    const float* bh = (const float*)d_in[11];
    float* out = (float*)d_out;

    // Phase 0: zero scratch (4.8M float4 for g_buf; cnt folded in)
    {
        int total = 3 * NN * DIM / 4;
        int grid = (total + 255) / 256;
        zero_kernel<<<grid, 256>>>();
    }
    // Phase 0b: weight concat
    wprep_kernel<<<(4 * DIM * DIM) / 256, 256>>>(W0, W1, W2, Wh);

    // Phase 1: edge scatter — one warp per edge
    {
        int grid = EE / 8;   // 8 warps (edges) per 256-thread block
        scatter_kernel<<<grid, 256>>>((const float4*)n_feats, src, dst, e_feats);
    }

    // Phase 2: fused GEMM + bias epilogue
    {
        int grid = (NN + 63) / 64;   // 782
        gemm_kernel<<<grid, 256>>>(n_feats, b0, b1, b2, bh, out);
    }
}

// round 6
// speedup vs baseline: 1.0194x; 1.0141x over previous
#include <cuda_runtime.h>
#include <cstdint>

#define NN 50000
#define EE 800000
#define DIM 128

// Scratch (static device globals — no allocation at launch time).
__device__ float g_buf[3u * NN * DIM];        // per-type src-sum accumulators, 76.8 MB
__device__ float cnt_buf[3u * NN];            // per-type in-degree counts (float, exact)
__device__ float wcat_buf[4 * DIM * DIM];     // concatenated weights, [k][o] layout, k=0..511

// ---------------------------------------------------------------------------
// Phase 0: zero accumulators
// ---------------------------------------------------------------------------
__global__ void zero_kernel() {
    const float4 z = make_float4(0.f, 0.f, 0.f, 0.f);
    size_t i = (size_t)blockIdx.x * blockDim.x + threadIdx.x;
    const size_t ng = (size_t)3 * NN * DIM / 4;   // 4.8M float4
    if (i < ng) reinterpret_cast<float4*>(g_buf)[i] = z;
    if (i < (size_t)(3 * NN) / 4) reinterpret_cast<float4*>(cnt_buf)[i] = z;
}

// ---------------------------------------------------------------------------
// Phase 0b: build Wcat[k][o] = W_{k/128}[o][k%128]  (k-major, o contiguous)
// ---------------------------------------------------------------------------
__global__ void wprep_kernel(const float* __restrict__ W0, const float* __restrict__ W1,
                             const float* __restrict__ W2, const float* __restrict__ Wh) {
    int idx = blockIdx.x * blockDim.x + threadIdx.x;   // < 512*128
    int k = idx >> 7;          // 0..511
    int o = idx & 127;
    int t = k >> 7;            // segment 0..3
    int kk = k & 127;
    const float* W = (t == 0) ? W0 : (t == 1) ? W1 : (t == 2) ? W2 : Wh;
    wcat_buf[idx] = W[o * DIM + kk];
}

// ---------------------------------------------------------------------------
// Phase 1: edge scatter. One warp per edge.
//   G_t[dst] += x[src];  cnt_t[dst] += 1     (the -cnt*x[dst] term is fused
//   into the GEMM A-loader — saves the x[dst] read here, 410 MB of L2 traffic)
// ---------------------------------------------------------------------------
__global__ __launch_bounds__(256) void scatter_kernel(
    const float4* __restrict__ x4,
    const int* __restrict__ src, const int* __restrict__ dst,
    const int* __restrict__ et) {
    int warp = (int)(((size_t)blockIdx.x * blockDim.x + threadIdx.x) >> 5);
    int lane = threadIdx.x & 31;
    if (warp >= EE) return;
    int s = __ldg(src + warp);
    int d = __ldg(dst + warp);
    int t = __ldg(et + warp);

    float4 a = x4[(size_t)s * 32 + lane];

    float* p = g_buf + ((size_t)t * NN + d) * DIM + lane * 4;
    asm volatile("red.global.add.v4.f32 [%0], {%1, %2, %3, %4};"
                 :: "l"(p), "f"(a.x), "f"(a.y), "f"(a.z), "f"(a.w) : "memory");

    if (lane == 0) atomicAdd(cnt_buf + (size_t)t * NN + d, 1.0f);
}

// ---------------------------------------------------------------------------
// Phase 2: out[N,128] = A[N,512] @ Wcat[512,128] + bias(counts)
//   A[v, k] = G_t[v][kk] - cnt_t[v]*x[v][kk]   for t = k/128 < 3
//           = x[v][k-384]                      for k >= 384
// Tiling: BM=128 x BN=128, BK=16, 256 threads, 8x8 microtile,
// register-staged double buffering.
// ---------------------------------------------------------------------------
__global__ __launch_bounds__(256, 2) void gemm_kernel(
    const float* __restrict__ x,
    const float* __restrict__ b0, const float* __restrict__ b1,
    const float* __restrict__ b2, const float* __restrict__ bh,
    float* __restrict__ out) {
    __shared__ float As[2][16][132];    // [buf][k][m], padded
    __shared__ float Bs[2][16][128];    // [buf][k][n]
    __shared__ float cs[3][128];
    __shared__ float bias_s[4][128];

    const int tid = threadIdx.x;
    const int node0 = blockIdx.x * 128;

    if (tid < 128) {
        bias_s[0][tid] = b0[tid];
        bias_s[1][tid] = b1[tid];
        bias_s[2][tid] = b2[tid];
        bias_s[3][tid] = bh[tid];
        int v = node0 + tid;
        bool ok = v < NN;
        cs[0][tid] = ok ? cnt_buf[0 * NN + v] : 0.f;
        cs[1][tid] = ok ? cnt_buf[1 * NN + v] : 0.f;
        cs[2][tid] = ok ? cnt_buf[2 * NN + v] : 0.f;
    }
    __syncthreads();   // cs needed by fetchA below

    const int m0 = (tid >> 4) << 3;      // 0..120
    const int n0 = (tid & 15) << 3;      // 0..120

    // staging registers
    float4 ra[2], rb[2];

    // ---- global fetch to registers ----
    auto fetchA = [&](int kt) {
        const int seg = kt >> 3;                 // 0..3, uniform per kt
#pragma unroll
        for (int r = 0; r < 2; r++) {
            int f = tid + r * 256;               // 0..511
            int row = f >> 2;                    // 0..127
            int q = f & 3;
            int v = node0 + row;
            int kk = ((kt & 7) << 4) + (q << 2); // 0..124
            float4 val = make_float4(0.f, 0.f, 0.f, 0.f);
            if (v < NN) {
                const float4* xp = reinterpret_cast<const float4*>(
                    x + (size_t)v * DIM + kk);
                if (seg < 3) {
                    const float4* gp = reinterpret_cast<const float4*>(
                        g_buf + ((size_t)seg * NN + v) * DIM + kk);
                    float4 g = __ldg(gp);
                    float4 xv = __ldg(xp);
                    float c = cs[seg][row];
                    val.x = fmaf(-c, xv.x, g.x);
                    val.y = fmaf(-c, xv.y, g.y);
                    val.z = fmaf(-c, xv.z, g.z);
                    val.w = fmaf(-c, xv.w, g.w);
                } else {
                    val = __ldg(xp);
                }
            }
            ra[r] = val;
        }
    };
    auto fetchB = [&](int kt) {
#pragma unroll
        for (int r = 0; r < 2; r++) {
            int f = tid + r * 256;
            int k = f >> 5;                      // 0..15
            int o = (f & 31) << 2;               // 0..124
            rb[r] = *reinterpret_cast<const float4*>(
                wcat_buf + (size_t)(kt * 16 + k) * DIM + o);
        }
    };
    // ---- register -> smem stores ----
    auto storeA = [&](int buf) {
#pragma unroll
        for (int r = 0; r < 2; r++) {
            int f = tid + r * 256;
            int row = f >> 2;
            int q = f & 3;
            As[buf][q * 4 + 0][row] = ra[r].x;
            As[buf][q * 4 + 1][row] = ra[r].y;
            As[buf][q * 4 + 2][row] = ra[r].z;
            As[buf][q * 4 + 3][row] = ra[r].w;
        }
    };
    auto storeB = [&](int buf) {
#pragma unroll
        for (int r = 0; r < 2; r++) {
            int f = tid + r * 256;
            int k = f >> 5;
            int o = (f & 31) << 2;
            *reinterpret_cast<float4*>(&Bs[buf][k][o]) = rb[r];
        }
    };

    float acc[8][8];
#pragma unroll
    for (int i = 0; i < 8; i++)
#pragma unroll
        for (int j = 0; j < 8; j++) acc[i][j] = 0.f;

    fetchA(0); fetchB(0);
    storeA(0); storeB(0);
    __syncthreads();

    for (int kt = 0; kt < 32; kt++) {
        int cur = kt & 1;
        int nxt = cur ^ 1;
        if (kt < 31) { fetchA(kt + 1); fetchB(kt + 1); }  // LDGs in flight

#pragma unroll
        for (int k = 0; k < 16; k++) {
            float4 a0 = *reinterpret_cast<const float4*>(&As[cur][k][m0]);
            float4 a1 = *reinterpret_cast<const float4*>(&As[cur][k][m0 + 4]);
            float4 w0 = *reinterpret_cast<const float4*>(&Bs[cur][k][n0]);
            float4 w1 = *reinterpret_cast<const float4*>(&Bs[cur][k][n0 + 4]);
            float af[8] = {a0.x, a0.y, a0.z, a0.w, a1.x, a1.y, a1.z, a1.w};
            float bf[8] = {w0.x, w0.y, w0.z, w0.w, w1.x, w1.y, w1.z, w1.w};
#pragma unroll
            for (int i = 0; i < 8; i++)
#pragma unroll
                for (int j = 0; j < 8; j++)
                    acc[i][j] = fmaf(af[i], bf[j], acc[i][j]);
        }

        if (kt < 31) { storeA(nxt); storeB(nxt); }
        __syncthreads();
    }

    // ---- epilogue: count-weighted biases, store ----
#pragma unroll
    for (int i = 0; i < 8; i++) {
        int row = m0 + i;
        int v = node0 + row;
        if (v < NN) {
            float c0 = cs[0][row];
            float c1 = cs[1][row];
            float c2 = cs[2][row];
            float res[8];
#pragma unroll
            for (int j = 0; j < 8; j++) {
                int o = n0 + j;
                res[j] = acc[i][j]
                       + c0 * bias_s[0][o]
                       + c1 * bias_s[1][o]
                       + c2 * bias_s[2][o]
                       + bias_s[3][o];
            }
            float* op = out + (size_t)v * DIM + n0;
            *reinterpret_cast<float4*>(op)     = make_float4(res[0], res[1], res[2], res[3]);
            *reinterpret_cast<float4*>(op + 4) = make_float4(res[4], res[5], res[6], res[7]);
        }
    }
}

// ---------------------------------------------------------------------------
// Launch
// ---------------------------------------------------------------------------
extern "C" void kernel_launch(void* const* d_in, const int* in_sizes, int n_in,
                              void* d_out, int out_size) {
    const float* n_feats = (const float*)d_in[0];
    const int*   src     = (const int*)d_in[1];
    const int*   dst     = (const int*)d_in[2];
    const int*   e_feats = (const int*)d_in[3];
    const float* W0 = (const float*)d_in[4];
    const float* b0 = (const float*)d_in[5];
    const float* W1 = (const float*)d_in[6];
    const float* b1 = (const float*)d_in[7];
    const float* W2 = (const float*)d_in[8];
    const float* b2 = (const float*)d_in[9];
    const float* Wh = (const float*)d_in[10];
    const float* bh = (const float*)d_in[11];
    float* out = (float*)d_out;

    // Phase 0: zero scratch
    {
        int total = 3 * NN * DIM / 4;
        int grid = (total + 255) / 256;
        zero_kernel<<<grid, 256>>>();
    }
    // Phase 0b: weight concat
    wprep_kernel<<<(4 * DIM * DIM) / 256, 256>>>(W0, W1, W2, Wh);

    // Phase 1: edge scatter — one warp per edge (src-only reads)
    {
        int grid = EE / 8;   // 8 warps (edges) per 256-thread block
        scatter_kernel<<<grid, 256>>>((const float4*)n_feats, src, dst, e_feats);
    }

    // Phase 2: fused GEMM + (−cnt·x) correction + bias epilogue
    {
        int grid = (NN + 127) / 128;   // 391
        gemm_kernel<<<grid, 256>>>(n_feats, b0, b1, b2, bh, out);
    }
}

// round 8
// speedup vs baseline: 1.2517x; 1.2279x over previous
#include <cuda_runtime.h>
#include <cstdint>

#define NN 50000
#define EE 800000
#define DIM 128

// Scratch (static device globals — no allocation at launch time).
__device__ float g_buf[3u * NN * DIM];        // per-type src-sum accumulators, 76.8 MB
__device__ float cnt_buf[3u * NN];            // per-type in-degree counts (float, exact)
__device__ float wcat_buf[4 * DIM * DIM];     // concatenated weights, [k][o] layout, k=0..511

// ---------------------------------------------------------------------------
// Phase 0: zero accumulators
// ---------------------------------------------------------------------------
__global__ void zero_kernel() {
    const float4 z = make_float4(0.f, 0.f, 0.f, 0.f);
    size_t i = (size_t)blockIdx.x * blockDim.x + threadIdx.x;
    const size_t ng = (size_t)3 * NN * DIM / 4;   // 4.8M float4
    if (i < ng) reinterpret_cast<float4*>(g_buf)[i] = z;
    if (i < (size_t)(3 * NN) / 4) reinterpret_cast<float4*>(cnt_buf)[i] = z;
}

// ---------------------------------------------------------------------------
// Phase 0b: build Wcat[k][o] = W_{k/128}[o][k%128]  (k-major, o contiguous)
// ---------------------------------------------------------------------------
__global__ void wprep_kernel(const float* __restrict__ W0, const float* __restrict__ W1,
                             const float* __restrict__ W2, const float* __restrict__ Wh) {
    int idx = blockIdx.x * blockDim.x + threadIdx.x;   // < 512*128
    int k = idx >> 7;          // 0..511
    int o = idx & 127;
    int t = k >> 7;            // segment 0..3
    int kk = k & 127;
    const float* W = (t == 0) ? W0 : (t == 1) ? W1 : (t == 2) ? W2 : Wh;
    wcat_buf[idx] = W[o * DIM + kk];
}

// ---------------------------------------------------------------------------
// Phase 1: edge scatter. One warp per edge.
//   G_t[dst] += x[src];  cnt_t[dst] += 1     (−cnt·x[dst] fused into GEMM)
// ---------------------------------------------------------------------------
__global__ __launch_bounds__(256) void scatter_kernel(
    const float4* __restrict__ x4,
    const int* __restrict__ src, const int* __restrict__ dst,
    const int* __restrict__ et) {
    int warp = (int)(((size_t)blockIdx.x * blockDim.x + threadIdx.x) >> 5);
    int lane = threadIdx.x & 31;
    if (warp >= EE) return;
    int s = __ldg(src + warp);
    int d = __ldg(dst + warp);
    int t = __ldg(et + warp);

    float4 a = x4[(size_t)s * 32 + lane];

    float* p = g_buf + ((size_t)t * NN + d) * DIM + lane * 4;
    asm volatile("red.global.add.v4.f32 [%0], {%1, %2, %3, %4};"
                 :: "l"(p), "f"(a.x), "f"(a.y), "f"(a.z), "f"(a.w) : "memory");

    if (lane == 0) atomicAdd(cnt_buf + (size_t)t * NN + d, 1.0f);
}

// ---------------------------------------------------------------------------
// f32x2 packed FMA helpers (sm_100+; bit-identical to two scalar fp32 FMAs).
// Packed pairs are carried as untyped b64 ("l" constraint) — ptxas rejects
// .f64-typed ("d") operands on fma.rn.f32x2.
// ---------------------------------------------------------------------------
using u64 = unsigned long long;

__device__ __forceinline__ void ffma2(u64& acc, u64 a, u64 b) {
    asm("fma.rn.f32x2 %0, %1, %2, %0;" : "+l"(acc) : "l"(a), "l"(b));
}
__device__ __forceinline__ u64 dup_f32(float v) {
    u64 r;
    asm("mov.b64 %0, {%1, %1};" : "=l"(r) : "f"(v));
    return r;
}
__device__ __forceinline__ void unpack2(u64 d, float& lo, float& hi) {
    asm("mov.b64 {%0, %1}, %2;" : "=f"(lo), "=f"(hi) : "l"(d));
}

// ---------------------------------------------------------------------------
// Phase 2: out[N,128] = A[N,512] @ Wcat[512,128] + bias(counts)
//   A[v, k] = G_t[v][kk] - cnt_t[v]*x[v][kk]   for t = k/128 < 3
//           = x[v][k-384]                      for k >= 384
// BM=128 x BN=128, BK=16, 256 threads, 8x8 microtile packed along m
// (f32x2 FMA), register-staged double buffering.
// ---------------------------------------------------------------------------
__global__ __launch_bounds__(256, 2) void gemm_kernel(
    const float* __restrict__ x,
    const float* __restrict__ b0, const float* __restrict__ b1,
    const float* __restrict__ b2, const float* __restrict__ bh,
    float* __restrict__ out) {
    __shared__ float As[2][16][132];    // [buf][k][m], pad 132 (33 float4) keeps
                                        // 16B alignment per row, kills conflicts
    __shared__ float Bs[2][16][128];    // [buf][k][n]
    __shared__ float cs[3][128];
    __shared__ float bias_s[4][128];

    const int tid = threadIdx.x;
    const int node0 = blockIdx.x * 128;

    if (tid < 128) {
        bias_s[0][tid] = b0[tid];
        bias_s[1][tid] = b1[tid];
        bias_s[2][tid] = b2[tid];
        bias_s[3][tid] = bh[tid];
        int v = node0 + tid;
        bool ok = v < NN;
        cs[0][tid] = ok ? cnt_buf[0 * NN + v] : 0.f;
        cs[1][tid] = ok ? cnt_buf[1 * NN + v] : 0.f;
        cs[2][tid] = ok ? cnt_buf[2 * NN + v] : 0.f;
    }
    __syncthreads();   // cs needed by fetchA below

    const int m0 = (tid >> 4) << 3;      // 0..120
    const int n0 = (tid & 15) << 3;      // 0..120

    // staging registers
    float4 ra[2], rb[2];

    // ---- global fetch to registers ----
    auto fetchA = [&](int kt) {
        const int seg = kt >> 3;                 // 0..3, uniform per kt
#pragma unroll
        for (int r = 0; r < 2; r++) {
            int f = tid + r * 256;               // 0..511
            int row = f >> 2;                    // 0..127
            int q = f & 3;
            int v = node0 + row;
            int kk = ((kt & 7) << 4) + (q << 2); // 0..124
            float4 val = make_float4(0.f, 0.f, 0.f, 0.f);
            if (v < NN) {
                const float4* xp = reinterpret_cast<const float4*>(
                    x + (size_t)v * DIM + kk);
                if (seg < 3) {
                    const float4* gp = reinterpret_cast<const float4*>(
                        g_buf + ((size_t)seg * NN + v) * DIM + kk);
                    float4 g = __ldg(gp);
                    float4 xv = __ldg(xp);
                    float c = cs[seg][row];
                    val.x = fmaf(-c, xv.x, g.x);
                    val.y = fmaf(-c, xv.y, g.y);
                    val.z = fmaf(-c, xv.z, g.z);
                    val.w = fmaf(-c, xv.w, g.w);
                } else {
                    val = __ldg(xp);
                }
            }
            ra[r] = val;
        }
    };
    auto fetchB = [&](int kt) {
#pragma unroll
        for (int r = 0; r < 2; r++) {
            int f = tid + r * 256;
            int k = f >> 5;                      // 0..15
            int o = (f & 31) << 2;               // 0..124
            rb[r] = *reinterpret_cast<const float4*>(
                wcat_buf + (size_t)(kt * 16 + k) * DIM + o);
        }
    };
    // ---- register -> smem stores ----
    auto storeA = [&](int buf) {
#pragma unroll
        for (int r = 0; r < 2; r++) {
            int f = tid + r * 256;
            int row = f >> 2;
            int q = f & 3;
            As[buf][q * 4 + 0][row] = ra[r].x;
            As[buf][q * 4 + 1][row] = ra[r].y;
            As[buf][q * 4 + 2][row] = ra[r].z;
            As[buf][q * 4 + 3][row] = ra[r].w;
        }
    };
    auto storeB = [&](int buf) {
#pragma unroll
        for (int r = 0; r < 2; r++) {
            int f = tid + r * 256;
            int k = f >> 5;
            int o = (f & 31) << 2;
            *reinterpret_cast<float4*>(&Bs[buf][k][o]) = rb[r];
        }
    };

    // acc2[mi][j]: packed pair (m = m0+2*mi, m0+2*mi+1), output column n0+j
    u64 acc2[4][8];
#pragma unroll
    for (int i = 0; i < 4; i++)
#pragma unroll
        for (int j = 0; j < 8; j++) acc2[i][j] = 0ull;

    fetchA(0); fetchB(0);
    storeA(0); storeB(0);
    __syncthreads();

    for (int kt = 0; kt < 32; kt++) {
        int cur = kt & 1;
        int nxt = cur ^ 1;
        if (kt < 31) { fetchA(kt + 1); fetchB(kt + 1); }  // LDGs in flight

#pragma unroll
        for (int k = 0; k < 16; k++) {
            // A pairs come out of smem already packed as f32x2 in b64 lanes
            ulonglong2 A0 = *reinterpret_cast<const ulonglong2*>(&As[cur][k][m0]);
            ulonglong2 A1 = *reinterpret_cast<const ulonglong2*>(&As[cur][k][m0 + 4]);
            float4 w0 = *reinterpret_cast<const float4*>(&Bs[cur][k][n0]);
            float4 w1 = *reinterpret_cast<const float4*>(&Bs[cur][k][n0 + 4]);
            u64 ap[4] = {A0.x, A0.y, A1.x, A1.y};
            float bf[8] = {w0.x, w0.y, w0.z, w0.w, w1.x, w1.y, w1.z, w1.w};
#pragma unroll
            for (int j = 0; j < 8; j++) {
                u64 bd = dup_f32(bf[j]);
#pragma unroll
                for (int mi = 0; mi < 4; mi++)
                    ffma2(acc2[mi][j], ap[mi], bd);
            }
        }

        if (kt < 31) { storeA(nxt); storeB(nxt); }
        __syncthreads();
    }

    // ---- epilogue: unpack, count-weighted biases, store ----
#pragma unroll
    for (int mi = 0; mi < 4; mi++) {
#pragma unroll
        for (int half = 0; half < 2; half++) {
            int row = m0 + 2 * mi + half;
            int v = node0 + row;
            if (v < NN) {
                float c0 = cs[0][row];
                float c1 = cs[1][row];
                float c2 = cs[2][row];
                float res[8];
#pragma unroll
                for (int j = 0; j < 8; j++) {
                    float lo, hi;
                    unpack2(acc2[mi][j], lo, hi);
                    float a = half ? hi : lo;
                    int o = n0 + j;
                    res[j] = a
                           + c0 * bias_s[0][o]
                           + c1 * bias_s[1][o]
                           + c2 * bias_s[2][o]
                           + bias_s[3][o];
                }
                float* op = out + (size_t)v * DIM + n0;
                *reinterpret_cast<float4*>(op)     = make_float4(res[0], res[1], res[2], res[3]);
                *reinterpret_cast<float4*>(op + 4) = make_float4(res[4], res[5], res[6], res[7]);
            }
        }
    }
}

// ---------------------------------------------------------------------------
// Launch
// ---------------------------------------------------------------------------
extern "C" void kernel_launch(void* const* d_in, const int* in_sizes, int n_in,
                              void* d_out, int out_size) {
    const float* n_feats = (const float*)d_in[0];
    const int*   src     = (const int*)d_in[1];
    const int*   dst     = (const int*)d_in[2];
    const int*   e_feats = (const int*)d_in[3];
    const float* W0 = (const float*)d_in[4];
    const float* b0 = (const float*)d_in[5];
    const float* W1 = (const float*)d_in[6];
    const float* b1 = (const float*)d_in[7];
    const float* W2 = (const float*)d_in[8];
    const float* b2 = (const float*)d_in[9];
    const float* Wh = (const float*)d_in[10];
    const float* bh = (const float*)d_in[11];
    float* out = (float*)d_out;

    // Phase 0: zero scratch
    {
        int total = 3 * NN * DIM / 4;
        int grid = (total + 255) / 256;
        zero_kernel<<<grid, 256>>>();
    }
    // Phase 0b: weight concat
    wprep_kernel<<<(4 * DIM * DIM) / 256, 256>>>(W0, W1, W2, Wh);

    // Phase 1: edge scatter — one warp per edge (src-only reads)
    {
        int grid = EE / 8;   // 8 warps (edges) per 256-thread block
        scatter_kernel<<<grid, 256>>>((const float4*)n_feats, src, dst, e_feats);
    }

    // Phase 2: fused GEMM (f32x2 packed FMA) + (−cnt·x) correction + biases
    {
        int grid = (NN + 127) / 128;   // 391
        gemm_kernel<<<grid, 256>>>(n_feats, b0, b1, b2, bh, out);
    }
}

// round 9
// speedup vs baseline: 1.3379x; 1.0689x over previous
#include <cuda_runtime.h>
#include <cstdint>

#define NN 50000
#define EE 800000
#define DIM 128

// Scratch (static device globals — no allocation at launch time).
__device__ float g_buf[3u * NN * DIM];        // per-type src-sum accumulators, 76.8 MB
__device__ float cnt_buf[3u * NN];            // per-type in-degree counts (float, exact)
__device__ float wcat_buf[4 * DIM * DIM];     // concatenated weights, [k][o] layout, k=0..511

// ---------------------------------------------------------------------------
// Phase 0: zero accumulators
// ---------------------------------------------------------------------------
__global__ void zero_kernel() {
    const float4 z = make_float4(0.f, 0.f, 0.f, 0.f);
    size_t i = (size_t)blockIdx.x * blockDim.x + threadIdx.x;
    const size_t ng = (size_t)3 * NN * DIM / 4;   // 4.8M float4
    if (i < ng) reinterpret_cast<float4*>(g_buf)[i] = z;
    if (i < (size_t)(3 * NN) / 4) reinterpret_cast<float4*>(cnt_buf)[i] = z;
}

// ---------------------------------------------------------------------------
// Phase 0b: build Wcat[k][o] = W_{k/128}[o][k%128]  (k-major, o contiguous)
// ---------------------------------------------------------------------------
__global__ void wprep_kernel(const float* __restrict__ W0, const float* __restrict__ W1,
                             const float* __restrict__ W2, const float* __restrict__ Wh) {
    int idx = blockIdx.x * blockDim.x + threadIdx.x;   // < 512*128
    int k = idx >> 7;          // 0..511
    int o = idx & 127;
    int t = k >> 7;            // segment 0..3
    int kk = k & 127;
    const float* W = (t == 0) ? W0 : (t == 1) ? W1 : (t == 2) ? W2 : Wh;
    wcat_buf[idx] = W[o * DIM + kk];
}

// ---------------------------------------------------------------------------
// Phase 1: edge scatter. One warp per edge.
//   G_t[dst] += x[src];  cnt_t[dst] += 1     (−cnt·x[dst] fused into GEMM)
// ---------------------------------------------------------------------------
__global__ __launch_bounds__(256) void scatter_kernel(
    const float4* __restrict__ x4,
    const int* __restrict__ src, const int* __restrict__ dst,
    const int* __restrict__ et) {
    int warp = (int)(((size_t)blockIdx.x * blockDim.x + threadIdx.x) >> 5);
    int lane = threadIdx.x & 31;
    if (warp >= EE) return;
    int s = __ldg(src + warp);
    int d = __ldg(dst + warp);
    int t = __ldg(et + warp);

    float4 a = x4[(size_t)s * 32 + lane];

    float* p = g_buf + ((size_t)t * NN + d) * DIM + lane * 4;
    asm volatile("red.global.add.v4.f32 [%0], {%1, %2, %3, %4};"
                 :: "l"(p), "f"(a.x), "f"(a.y), "f"(a.z), "f"(a.w) : "memory");

    if (lane == 0) atomicAdd(cnt_buf + (size_t)t * NN + d, 1.0f);
}

// ---------------------------------------------------------------------------
// f32x2 packed FMA helpers (sm_100+; bit-identical to two scalar fp32 FMAs).
// b64 ("l") operands — ptxas rejects .f64-typed ("d") on fma.rn.f32x2.
// ---------------------------------------------------------------------------
using u64 = unsigned long long;

__device__ __forceinline__ void ffma2(u64& acc, u64 a, u64 b) {
    asm("fma.rn.f32x2 %0, %1, %2, %0;" : "+l"(acc) : "l"(a), "l"(b));
}
__device__ __forceinline__ u64 dup_f32(float v) {
    u64 r;
    asm("mov.b64 %0, {%1, %1};" : "=l"(r) : "f"(v));
    return r;
}
__device__ __forceinline__ void unpack2(u64 d, float& lo, float& hi) {
    asm("mov.b64 {%0, %1}, %2;" : "=f"(lo), "=f"(hi) : "l"(d));
}

// ---------------------------------------------------------------------------
// Phase 2: out[N,128] = A[N,512] @ Wcat[512,128] + bias(counts)
//   A[v, k] = G_t[v][kk] - cnt_t[v]*x[v][kk]   for t = k/128 < 3
//           = x[v][k-384]                      for k >= 384
// BM=128 x BN=64 (grid = m-tiles x 2 n-halves), BK=16, 256 threads,
// 8m(packed f32x2)x4n microtile -> 32 acc regs, 3 CTAs/SM, no spills.
// ---------------------------------------------------------------------------
__global__ __launch_bounds__(256, 3) void gemm_kernel(
    const float* __restrict__ x,
    const float* __restrict__ b0, const float* __restrict__ b1,
    const float* __restrict__ b2, const float* __restrict__ bh,
    float* __restrict__ out) {
    __shared__ float As[2][16][132];    // [buf][k][m], padded
    __shared__ float Bs[2][16][64];     // [buf][k][n]
    __shared__ float cs[3][128];
    __shared__ float bias_s[4][64];

    const int tid = threadIdx.x;
    const int node0 = (blockIdx.x >> 1) * 128;
    const int nbase = (blockIdx.x & 1) * 64;

    if (tid < 128) {
        int v = node0 + tid;
        int vc = v < NN ? v : (NN - 1);
        bool ok = v < NN;
        cs[0][tid] = ok ? cnt_buf[0 * NN + vc] : 0.f;
        cs[1][tid] = ok ? cnt_buf[1 * NN + vc] : 0.f;
        cs[2][tid] = ok ? cnt_buf[2 * NN + vc] : 0.f;
    }
    {   // bias: 4 segments x 64 cols
        int t = tid >> 6;          // 0..3
        int o = tid & 63;
        const float* bp = (t == 0) ? b0 : (t == 1) ? b1 : (t == 2) ? b2 : bh;
        bias_s[t][o] = bp[nbase + o];
    }
    __syncthreads();   // cs needed by fetchA below

    const int m0 = (tid >> 4) << 3;      // 0..120
    const int n0 = (tid & 15) << 2;      // 0..60

    // staging registers
    float4 ra[2], rb;

    // A-load mapping: 512 float4 over 256 threads x2
    // B-load mapping: 256 float4 over 256 threads x1
    auto fetchA = [&](int kt) {
        const int seg = kt >> 3;                 // 0..3, uniform per kt
#pragma unroll
        for (int r = 0; r < 2; r++) {
            int f = tid + r * 256;               // 0..511
            int row = f >> 2;                    // 0..127
            int q = f & 3;
            int v = node0 + row;
            int vc = v < NN ? v : (NN - 1);      // clamp: branch-free
            int kk = ((kt & 7) << 4) + (q << 2); // 0..124
            const float4* xp = reinterpret_cast<const float4*>(
                x + (size_t)vc * DIM + kk);
            if (seg < 3) {
                const float4* gp = reinterpret_cast<const float4*>(
                    g_buf + ((size_t)seg * NN + vc) * DIM + kk);
                float4 g = __ldg(gp);
                float4 xv = __ldg(xp);
                float c = cs[seg][row];
                ra[r].x = fmaf(-c, xv.x, g.x);
                ra[r].y = fmaf(-c, xv.y, g.y);
                ra[r].z = fmaf(-c, xv.z, g.z);
                ra[r].w = fmaf(-c, xv.w, g.w);
            } else {
                ra[r] = __ldg(xp);
            }
        }
    };
    auto fetchB = [&](int kt) {
        int k = tid >> 4;                        // 0..15
        int o = (tid & 15) << 2;                 // 0..60
        rb = *reinterpret_cast<const float4*>(
            wcat_buf + (size_t)(kt * 16 + k) * DIM + nbase + o);
    };
    auto storeA = [&](int buf) {
#pragma unroll
        for (int r = 0; r < 2; r++) {
            int f = tid + r * 256;
            int row = f >> 2;
            int q = f & 3;
            As[buf][q * 4 + 0][row] = ra[r].x;
            As[buf][q * 4 + 1][row] = ra[r].y;
            As[buf][q * 4 + 2][row] = ra[r].z;
            As[buf][q * 4 + 3][row] = ra[r].w;
        }
    };
    auto storeB = [&](int buf) {
        int k = tid >> 4;
        int o = (tid & 15) << 2;
        *reinterpret_cast<float4*>(&Bs[buf][k][o]) = rb;
    };

    // acc2[mi][j]: packed m-pair (m0+2*mi, m0+2*mi+1), output col nbase+n0+j
    u64 acc2[4][4];
#pragma unroll
    for (int i = 0; i < 4; i++)
#pragma unroll
        for (int j = 0; j < 4; j++) acc2[i][j] = 0ull;

    fetchA(0); fetchB(0);
    storeA(0); storeB(0);
    __syncthreads();

    for (int kt = 0; kt < 32; kt++) {
        int cur = kt & 1;
        int nxt = cur ^ 1;
        if (kt < 31) { fetchA(kt + 1); fetchB(kt + 1); }  // LDGs in flight

#pragma unroll
        for (int k = 0; k < 16; k++) {
            ulonglong2 A0 = *reinterpret_cast<const ulonglong2*>(&As[cur][k][m0]);
            ulonglong2 A1 = *reinterpret_cast<const ulonglong2*>(&As[cur][k][m0 + 4]);
            float4 w0 = *reinterpret_cast<const float4*>(&Bs[cur][k][n0]);
            u64 ap[4] = {A0.x, A0.y, A1.x, A1.y};
            float bf[4] = {w0.x, w0.y, w0.z, w0.w};
#pragma unroll
            for (int j = 0; j < 4; j++) {
                u64 bd = dup_f32(bf[j]);
#pragma unroll
                for (int mi = 0; mi < 4; mi++)
                    ffma2(acc2[mi][j], ap[mi], bd);
            }
        }

        if (kt < 31) { storeA(nxt); storeB(nxt); }
        __syncthreads();
    }

    // ---- epilogue: unpack, count-weighted biases, store ----
#pragma unroll
    for (int mi = 0; mi < 4; mi++) {
#pragma unroll
        for (int half = 0; half < 2; half++) {
            int row = m0 + 2 * mi + half;
            int v = node0 + row;
            if (v < NN) {
                float c0 = cs[0][row];
                float c1 = cs[1][row];
                float c2 = cs[2][row];
                float res[4];
#pragma unroll
                for (int j = 0; j < 4; j++) {
                    float lo, hi;
                    unpack2(acc2[mi][j], lo, hi);
                    float a = half ? hi : lo;
                    int o = n0 + j;
                    res[j] = a
                           + c0 * bias_s[0][o]
                           + c1 * bias_s[1][o]
                           + c2 * bias_s[2][o]
                           + bias_s[3][o];
                }
                float* op = out + (size_t)v * DIM + nbase + n0;
                *reinterpret_cast<float4*>(op) = make_float4(res[0], res[1], res[2], res[3]);
            }
        }
    }
}

// ---------------------------------------------------------------------------
// Launch
// ---------------------------------------------------------------------------
extern "C" void kernel_launch(void* const* d_in, const int* in_sizes, int n_in,
                              void* d_out, int out_size) {
    const float* n_feats = (const float*)d_in[0];
    const int*   src     = (const int*)d_in[1];
    const int*   dst     = (const int*)d_in[2];
    const int*   e_feats = (const int*)d_in[3];
    const float* W0 = (const float*)d_in[4];
    const float* b0 = (const float*)d_in[5];
    const float* W1 = (const float*)d_in[6];
    const float* b1 = (const float*)d_in[7];
    const float* W2 = (const float*)d_in[8];
    const float* b2 = (const float*)d_in[9];
    const float* Wh = (const float*)d_in[10];
    const float* bh = (const float*)d_in[11];
    float* out = (float*)d_out;

    // Phase 0: zero scratch
    {
        int total = 3 * NN * DIM / 4;
        int grid = (total + 255) / 256;
        zero_kernel<<<grid, 256>>>();
    }
    // Phase 0b: weight concat
    wprep_kernel<<<(4 * DIM * DIM) / 256, 256>>>(W0, W1, W2, Wh);

    // Phase 1: edge scatter — one warp per edge (src-only reads)
    {
        int grid = EE / 8;   // 8 warps (edges) per 256-thread block
        scatter_kernel<<<grid, 256>>>((const float4*)n_feats, src, dst, e_feats);
    }

    // Phase 2: fused GEMM (f32x2, low-pressure 8x4 microtile) + biases
    {
        int grid = ((NN + 127) / 128) * 2;   // 782: m-tiles x 2 n-halves
        gemm_kernel<<<grid, 256>>>(n_feats, b0, b1, b2, bh, out);
    }
}